// round 14
// baseline (speedup 1.0000x reference)
#include <cuda_runtime.h>

// CumulantSOAP_CV: per-column mean & variance over X (200000 x 576 fp32),
// then project (cum - mu) @ W -> (1 x 4).
// pass1: R11 streaming loop (untouched) + fixed-point int64 atomicAdd of the
//        per-thread partials into [4][576] accumulators. Integer atomics are
//        exactly associative -> bitwise deterministic, no grid barrier, no
//        partial arrays, no second reduction pass.
// tail:  ONE tiny single-block kernel: exact int64 fold of the 4 phase rows,
//        convert, cumulants, projection, tree-reduce. Also resets the
//        accumulators for the next graph replay (stream-ordered: safe).

#define N_ROWS   200000
#define P        576
#define NBLK     296
#define RPB      ((N_ROWS + NBLK - 1) / NBLK)   // 676 rows per block

// Fixed-point scale: 2^40. Totals: sum| <~ 3e3, sumsq ~ 2e5 -> * 2^40 ~ 2.2e17,
// well inside int64. Quantization: <= 1184 * 2^-40 absolute -> ~1e-14 relative.
#define FXSCALE  1099511627776.0f               // 2^40
#define INVFX    (1.0 / 1099511627776.0)        // 2^-40 (double)

// Accumulators (allocation-free __device__ globals; zero-initialized at load,
// reset by tail_kernel after each use).
__device__ unsigned long long g_acc_s[4][P];
__device__ unsigned long long g_acc_q[4][P];

// ---------------------------------------------------------------------------
// Pass 1: streaming reduction over X. blockDim = 576, grid = 296 (2 CTA/SM).
// Loop BYTE-IDENTICAL to R11 (best measured). Epilogue: 8 fixed-point
// fire-and-forget atomicAdds per thread (REDG.ADD.64), 296 ops/address.
// ---------------------------------------------------------------------------
__global__ __launch_bounds__(576) void pass1_kernel(const float* __restrict__ X) {
    const int b  = blockIdx.x;
    const int t  = threadIdx.x;
    const int c4 = t % 144;      // float4 column index (0..143)
    const int rs = t / 144;      // 0..3

    const int r0 = b * RPB;
    int r1 = r0 + RPB;
    if (r1 > N_ROWS) r1 = N_ROWS;

    const float4* __restrict__ Xv = reinterpret_cast<const float4*>(X);

    float4 s = make_float4(0.f, 0.f, 0.f, 0.f);
    float4 q = make_float4(0.f, 0.f, 0.f, 0.f);

    #pragma unroll 4
    for (int r = r0 + rs; r < r1; r += 4) {
        float4 x = __ldcs(&Xv[(size_t)r * 144 + c4]);
        s.x += x.x; s.y += x.y; s.z += x.z; s.w += x.w;
        q.x += x.x * x.x; q.y += x.y * x.y; q.z += x.z * x.z; q.w += x.w * x.w;
    }

    // Fixed-point accumulate (deterministic: integer addition is associative).
    const int c0 = c4 * 4;
    atomicAdd(&g_acc_s[rs][c0 + 0], (unsigned long long)__float2ll_rn(s.x * FXSCALE));
    atomicAdd(&g_acc_s[rs][c0 + 1], (unsigned long long)__float2ll_rn(s.y * FXSCALE));
    atomicAdd(&g_acc_s[rs][c0 + 2], (unsigned long long)__float2ll_rn(s.z * FXSCALE));
    atomicAdd(&g_acc_s[rs][c0 + 3], (unsigned long long)__float2ll_rn(s.w * FXSCALE));
    atomicAdd(&g_acc_q[rs][c0 + 0], (unsigned long long)__float2ll_rn(q.x * FXSCALE));
    atomicAdd(&g_acc_q[rs][c0 + 1], (unsigned long long)__float2ll_rn(q.y * FXSCALE));
    atomicAdd(&g_acc_q[rs][c0 + 2], (unsigned long long)__float2ll_rn(q.z * FXSCALE));
    atomicAdd(&g_acc_q[rs][c0 + 3], (unsigned long long)__float2ll_rn(q.w * FXSCALE));
}

// ---------------------------------------------------------------------------
// Tail: ONE block, 576 threads. Thread t owns column t:
//   exact int64 fold of the 4 phase accumulators, convert to double->float,
//   cumulants, subtract mu, project by W (1728 x 4), tree-reduce to out[4].
//   Then reset the accumulators for the next graph replay.
// mom1 == 0 analytically (reference's fp32 residual ~1e-7 is negligible at
// the 1e-3 output tolerance).
// ---------------------------------------------------------------------------
__global__ __launch_bounds__(576) void tail_kernel(const float* __restrict__ mu,
                                                   const float* __restrict__ W,
                                                   float* __restrict__ out) {
    const int t = threadIdx.x;   // 0..575 = column

    long long si = 0, qi = 0;
    #pragma unroll
    for (int rs = 0; rs < 4; rs++) {
        si += (long long)g_acc_s[rs][t];
        qi += (long long)g_acc_q[rs][t];
    }
    // Reset for next replay (thread t touches only column t; stream order
    // guarantees this completes before the next pass1 launch).
    #pragma unroll
    for (int rs = 0; rs < 4; rs++) {
        g_acc_s[rs][t] = 0ull;
        g_acc_q[rs][t] = 0ull;
    }

    const float s2 = (float)((double)si * INVFX);
    const float q2 = (float)((double)qi * INVFX);

    const float invN = 1.0f / (float)N_ROWS;
    const float m    = s2 * invN;
    const float mom2 = q2 * invN - m * m;

    const int j0 = 3 * t;
    const float d0 = m    - mu[j0 + 0];
    const float d1 = 0.f  - mu[j0 + 1];
    const float d2 = mom2 - mu[j0 + 2];

    float4 acc;
    acc.x = d0 * W[(j0 + 0) * 4 + 0] + d1 * W[(j0 + 1) * 4 + 0] + d2 * W[(j0 + 2) * 4 + 0];
    acc.y = d0 * W[(j0 + 0) * 4 + 1] + d1 * W[(j0 + 1) * 4 + 1] + d2 * W[(j0 + 2) * 4 + 1];
    acc.z = d0 * W[(j0 + 0) * 4 + 2] + d1 * W[(j0 + 1) * 4 + 2] + d2 * W[(j0 + 2) * 4 + 2];
    acc.w = d0 * W[(j0 + 0) * 4 + 3] + d1 * W[(j0 + 1) * 4 + 3] + d2 * W[(j0 + 2) * 4 + 3];

    __shared__ float4 sh[576];
    sh[t] = acc;
    __syncthreads();

    if (t < 64) {
        float4 a = sh[t];
        for (int i = t + 64; i < 576; i += 64) {
            float4 bb = sh[i];
            a.x += bb.x; a.y += bb.y; a.z += bb.z; a.w += bb.w;
        }
        sh[t] = a;
    }
    __syncthreads();
    #pragma unroll
    for (int w = 32; w > 0; w >>= 1) {
        if (t < w) {
            float4 a = sh[t], bb = sh[t + w];
            a.x += bb.x; a.y += bb.y; a.z += bb.z; a.w += bb.w;
            sh[t] = a;
        }
        __syncthreads();
    }

    if (t == 0) {
        out[0] = sh[0].x;
        out[1] = sh[0].y;
        out[2] = sh[0].z;
        out[3] = sh[0].w;
    }
}

extern "C" void kernel_launch(void* const* d_in, const int* in_sizes, int n_in,
                              void* d_out, int out_size) {
    (void)in_sizes; (void)n_in; (void)out_size;
    const float* X  = (const float*)d_in[0];   // (200000, 576)
    const float* mu = (const float*)d_in[1];   // (1728,)
    const float* W  = (const float*)d_in[2];   // (1728, 4)
    float* out = (float*)d_out;                // (1, 4)

    pass1_kernel<<<NBLK, 576>>>(X);
    tail_kernel<<<1, 576>>>(mu, W, out);
}

// round 15
// speedup vs baseline: 1.1359x; 1.1359x over previous
#include <cuda_runtime.h>

// CumulantSOAP_CV: per-column mean & variance over X (200000 x 576 fp32),
// then project (cum - mu) @ W -> (1 x 4).
// pass1: byte-identical to R11 best (streaming + __ldcs, plain coalesced
//        4-phase partial stores, 35 regs).
// tail:  ticket-based "last block reduces": 74 blocks fold their slice and
//        take a ticket; ONLY the last-arriving block does the final fold +
//        projection. No grid barrier, no spinning, no idle parked blocks.

#define N_ROWS   200000
#define P        576
#define NBLK     296
#define RPB      ((N_ROWS + NBLK - 1) / NBLK)   // 676 rows per block
#define NPART    (NBLK * 4)                     // 1184 partial rows
#define NRED     74                              // tail blocks
#define ROWS_PER_RED (NPART / NRED)              // 16

// Scratch (allocation-free __device__ globals).
__device__ float g_ps [NPART][P];   // partial sums      (2.7 MB)
__device__ float g_pq [NPART][P];   // partial sum-sqs   (2.7 MB)
__device__ float g_ps2[NRED][P];
__device__ float g_pq2[NRED][P];
__device__ int   g_cnt;             // ticket; zero-init, reset by last block

// ---------------------------------------------------------------------------
// Pass 1: streaming reduction over X. blockDim = 576, grid = 296 (2 CTA/SM).
// BYTE-IDENTICAL to R11 (best measured: 80.4us total).
// ---------------------------------------------------------------------------
__global__ __launch_bounds__(576) void pass1_kernel(const float* __restrict__ X) {
    const int b  = blockIdx.x;
    const int t  = threadIdx.x;
    const int c4 = t % 144;      // float4 column index (0..143)
    const int rs = t / 144;      // 0..3

    const int r0 = b * RPB;
    int r1 = r0 + RPB;
    if (r1 > N_ROWS) r1 = N_ROWS;

    const float4* __restrict__ Xv = reinterpret_cast<const float4*>(X);

    float4 s = make_float4(0.f, 0.f, 0.f, 0.f);
    float4 q = make_float4(0.f, 0.f, 0.f, 0.f);

    #pragma unroll 4
    for (int r = r0 + rs; r < r1; r += 4) {
        float4 x = __ldcs(&Xv[(size_t)r * 144 + c4]);
        s.x += x.x; s.y += x.y; s.z += x.z; s.w += x.w;
        q.x += x.x * x.x; q.y += x.y * x.y; q.z += x.z * x.z; q.w += x.w * x.w;
    }

    const int p = b * 4 + rs;
    reinterpret_cast<float4*>(&g_ps[p][0])[c4] = s;
    reinterpret_cast<float4*>(&g_pq[p][0])[c4] = q;
}

// ---------------------------------------------------------------------------
// Tail kernel: 74 blocks x 576 threads. Thread layout (c4 = t%144, rs = t/144).
//  Stage A (all blocks): block b folds rows [16b, 16b+16); phase rs takes
//    rows 16b+rs+{0,4,8,12} -> 8 independent float4 loads. Phase-fold via
//    smem, coalesced float4 store to g_ps2/g_pq2. Fence, take ticket, exit.
//  Stage B (LAST block only, whichever it is): fold the 74 rows of
//    g_ps2/g_pq2 (fixed row order -> deterministic regardless of which block
//    runs it), cumulants, projection, tree-reduce, reset ticket.
// mom1 == 0 analytically (reference's fp32 residual ~1e-7 is negligible at
// the 1e-3 output tolerance).
// ---------------------------------------------------------------------------
__global__ __launch_bounds__(576) void tail_kernel(const float* __restrict__ mu,
                                                   const float* __restrict__ W,
                                                   float* __restrict__ out) {
    const int b  = blockIdx.x;    // 0..73
    const int t  = threadIdx.x;   // 0..575
    const int c4 = t % 144;
    const int rs = t / 144;       // 0..3

    __shared__ float4 park_s[3][144];
    __shared__ float4 park_q[3][144];
    __shared__ int    sh_last;

    // ---------------- Stage A: one round-trip fold of 16 rows --------------
    {
        const int i0 = b * ROWS_PER_RED + rs;   // rows i0, i0+4, i0+8, i0+12
        const float4 a0 = reinterpret_cast<const float4*>(&g_ps[i0     ][0])[c4];
        const float4 a1 = reinterpret_cast<const float4*>(&g_ps[i0 +  4][0])[c4];
        const float4 a2 = reinterpret_cast<const float4*>(&g_ps[i0 +  8][0])[c4];
        const float4 a3 = reinterpret_cast<const float4*>(&g_ps[i0 + 12][0])[c4];
        const float4 e0 = reinterpret_cast<const float4*>(&g_pq[i0     ][0])[c4];
        const float4 e1 = reinterpret_cast<const float4*>(&g_pq[i0 +  4][0])[c4];
        const float4 e2 = reinterpret_cast<const float4*>(&g_pq[i0 +  8][0])[c4];
        const float4 e3 = reinterpret_cast<const float4*>(&g_pq[i0 + 12][0])[c4];

        float4 s = make_float4((a0.x + a1.x) + (a2.x + a3.x),
                               (a0.y + a1.y) + (a2.y + a3.y),
                               (a0.z + a1.z) + (a2.z + a3.z),
                               (a0.w + a1.w) + (a2.w + a3.w));
        float4 q = make_float4((e0.x + e1.x) + (e2.x + e3.x),
                               (e0.y + e1.y) + (e2.y + e3.y),
                               (e0.z + e1.z) + (e2.z + e3.z),
                               (e0.w + e1.w) + (e2.w + e3.w));

        if (rs > 0) { park_s[rs - 1][c4] = s; park_q[rs - 1][c4] = q; }
        __syncthreads();
        if (rs == 0) {
            #pragma unroll
            for (int ph = 0; ph < 3; ph++) {
                float4 a = park_s[ph][c4];
                s.x += a.x; s.y += a.y; s.z += a.z; s.w += a.w;
                float4 e = park_q[ph][c4];
                q.x += e.x; q.y += e.y; q.z += e.z; q.w += e.w;
            }
            reinterpret_cast<float4*>(&g_ps2[b][0])[c4] = s;
            reinterpret_cast<float4*>(&g_pq2[b][0])[c4] = q;
        }
    }

    // ---------------- Ticket: last block continues, others exit -----------
    __threadfence();              // release our g_ps2/g_pq2 stores
    __syncthreads();
    if (t == 0) {
        const int ticket = atomicAdd(&g_cnt, 1);
        sh_last = (ticket == NRED - 1);
    }
    __syncthreads();
    if (!sh_last) return;

    __threadfence();              // acquire: all 74 blocks' stores visible

    // ---------------- Stage B: fold 74 rows (float4, phase-split) ---------
    float4 s = make_float4(0.f, 0.f, 0.f, 0.f);
    float4 q = make_float4(0.f, 0.f, 0.f, 0.f);
    #pragma unroll 5
    for (int i = rs; i < NRED; i += 4) {
        float4 a = reinterpret_cast<const float4*>(&g_ps2[i][0])[c4];
        s.x += a.x; s.y += a.y; s.z += a.z; s.w += a.w;
        float4 e = reinterpret_cast<const float4*>(&g_pq2[i][0])[c4];
        q.x += e.x; q.y += e.y; q.z += e.z; q.w += e.w;
    }
    __syncthreads();              // park_s/park_q reuse
    if (rs > 0) { park_s[rs - 1][c4] = s; park_q[rs - 1][c4] = q; }
    __syncthreads();

    __shared__ float4 tot_s[144];
    __shared__ float4 tot_q[144];
    if (rs == 0) {
        #pragma unroll
        for (int ph = 0; ph < 3; ph++) {
            float4 a = park_s[ph][c4];
            s.x += a.x; s.y += a.y; s.z += a.z; s.w += a.w;
            float4 e = park_q[ph][c4];
            q.x += e.x; q.y += e.y; q.z += e.z; q.w += e.w;
        }
        tot_s[c4] = s;
        tot_q[c4] = q;
    }
    __syncthreads();

    // ---------------- Cumulants + projection (thread t = column t) --------
    const float s2 = reinterpret_cast<const float*>(tot_s)[t];
    const float q2 = reinterpret_cast<const float*>(tot_q)[t];

    const float invN = 1.0f / (float)N_ROWS;
    const float m    = s2 * invN;
    const float mom2 = q2 * invN - m * m;

    const int j0 = 3 * t;
    const float d0 = m    - mu[j0 + 0];
    const float d1 = 0.f  - mu[j0 + 1];
    const float d2 = mom2 - mu[j0 + 2];

    float4 acc;
    acc.x = d0 * W[(j0 + 0) * 4 + 0] + d1 * W[(j0 + 1) * 4 + 0] + d2 * W[(j0 + 2) * 4 + 0];
    acc.y = d0 * W[(j0 + 0) * 4 + 1] + d1 * W[(j0 + 1) * 4 + 1] + d2 * W[(j0 + 2) * 4 + 1];
    acc.z = d0 * W[(j0 + 0) * 4 + 2] + d1 * W[(j0 + 1) * 4 + 2] + d2 * W[(j0 + 2) * 4 + 2];
    acc.w = d0 * W[(j0 + 0) * 4 + 3] + d1 * W[(j0 + 1) * 4 + 3] + d2 * W[(j0 + 2) * 4 + 3];

    __shared__ float4 sh3[576];
    sh3[t] = acc;
    __syncthreads();

    if (t < 64) {
        float4 a = sh3[t];
        for (int i = t + 64; i < 576; i += 64) {
            float4 bb = sh3[i];
            a.x += bb.x; a.y += bb.y; a.z += bb.z; a.w += bb.w;
        }
        sh3[t] = a;
    }
    __syncthreads();
    #pragma unroll
    for (int w = 32; w > 0; w >>= 1) {
        if (t < w) {
            float4 a = sh3[t], bb = sh3[t + w];
            a.x += bb.x; a.y += bb.y; a.z += bb.z; a.w += bb.w;
            sh3[t] = a;
        }
        __syncthreads();
    }

    if (t == 0) {
        out[0] = sh3[0].x;
        out[1] = sh3[0].y;
        out[2] = sh3[0].z;
        out[3] = sh3[0].w;
        g_cnt = 0;   // reset ticket for next graph replay (we are the last block)
    }
}

extern "C" void kernel_launch(void* const* d_in, const int* in_sizes, int n_in,
                              void* d_out, int out_size) {
    (void)in_sizes; (void)n_in; (void)out_size;
    const float* X  = (const float*)d_in[0];   // (200000, 576)
    const float* mu = (const float*)d_in[1];   // (1728,)
    const float* W  = (const float*)d_in[2];   // (1728, 4)
    float* out = (float*)d_out;                // (1, 4)

    pass1_kernel<<<NBLK, 576>>>(X);
    tail_kernel<<<NRED, 576>>>(mu, W, out);
}

// round 17
// speedup vs baseline: 1.1947x; 1.0517x over previous
#include <cuda_runtime.h>

// CumulantSOAP_CV: per-column mean & variance over X (200000 x 576 fp32),
// then project (cum - mu) @ W -> (1 x 4).
// R16 theory: register-starved MLP was capping BOTH kernels (pass1 regs=35,
// tail regs=32 -> ~2 float4 loads in flight). Fix: __launch_bounds__ with
// explicit minBlocks (raises ptxas reg budget) + explicitly batched loads.

#define N_ROWS   200000
#define P        576
#define NBLK     296
#define RPB      ((N_ROWS + NBLK - 1) / NBLK)   // 676 rows per block
#define NPART    (NBLK * 4)                     // 1184 partial rows
#define NRED     74                              // tail blocks
#define ROWS_PER_RED (NPART / NRED)              // 16

// Scratch (allocation-free __device__ globals).
__device__ float g_ps [NPART][P];   // partial sums      (2.7 MB)
__device__ float g_pq [NPART][P];   // partial sum-sqs   (2.7 MB)
__device__ float g_ps2[NRED][P];
__device__ float g_pq2[NRED][P];
__device__ int   g_cnt;             // ticket; zero-init, reset by last block

// ---------------------------------------------------------------------------
// Pass 1: streaming reduction over X. blockDim = 576, grid = 296 (2 CTA/SM).
// Same schedule as R11 best, but with minBlocks=2 (reg budget 56) and an
// explicitly batched 4x float4 load body so ptxas keeps 4 loads in flight.
// ---------------------------------------------------------------------------
__global__ __launch_bounds__(576, 2) void pass1_kernel(const float* __restrict__ X) {
    const int b  = blockIdx.x;
    const int t  = threadIdx.x;
    const int c4 = t % 144;      // float4 column index (0..143)
    const int rs = t / 144;      // 0..3

    const int r0 = b * RPB;
    int r1 = r0 + RPB;
    if (r1 > N_ROWS) r1 = N_ROWS;

    const float4* __restrict__ Xv = reinterpret_cast<const float4*>(X) + c4;

    float4 s = make_float4(0.f, 0.f, 0.f, 0.f);
    float4 q = make_float4(0.f, 0.f, 0.f, 0.f);

    int r = r0 + rs;
    // Batched body: 4 independent float4 loads issued before any consumption.
    for (; r + 12 < r1; r += 16) {
        const float4 x0 = __ldcs(&Xv[(size_t)(r     ) * 144]);
        const float4 x1 = __ldcs(&Xv[(size_t)(r +  4) * 144]);
        const float4 x2 = __ldcs(&Xv[(size_t)(r +  8) * 144]);
        const float4 x3 = __ldcs(&Xv[(size_t)(r + 12) * 144]);

        s.x += x0.x; s.y += x0.y; s.z += x0.z; s.w += x0.w;
        q.x += x0.x * x0.x; q.y += x0.y * x0.y; q.z += x0.z * x0.z; q.w += x0.w * x0.w;
        s.x += x1.x; s.y += x1.y; s.z += x1.z; s.w += x1.w;
        q.x += x1.x * x1.x; q.y += x1.y * x1.y; q.z += x1.z * x1.z; q.w += x1.w * x1.w;
        s.x += x2.x; s.y += x2.y; s.z += x2.z; s.w += x2.w;
        q.x += x2.x * x2.x; q.y += x2.y * x2.y; q.z += x2.z * x2.z; q.w += x2.w * x2.w;
        s.x += x3.x; s.y += x3.y; s.z += x3.z; s.w += x3.w;
        q.x += x3.x * x3.x; q.y += x3.y * x3.y; q.z += x3.z * x3.z; q.w += x3.w * x3.w;
    }
    for (; r < r1; r += 4) {
        const float4 x = __ldcs(&Xv[(size_t)r * 144]);
        s.x += x.x; s.y += x.y; s.z += x.z; s.w += x.w;
        q.x += x.x * x.x; q.y += x.y * x.y; q.z += x.z * x.z; q.w += x.w * x.w;
    }

    const int p = b * 4 + rs;
    reinterpret_cast<float4*>(&g_ps[p][0])[c4] = s;
    reinterpret_cast<float4*>(&g_pq[p][0])[c4] = q;
}

// ---------------------------------------------------------------------------
// Tail kernel: 74 blocks x 576 threads, ticket-based "last block reduces".
// minBlocks=1 -> reg budget 112 so stage A's 8 float4 loads batch fully.
//  Stage A: block b folds rows [16b,16b+16); phase rs takes rows
//    16b+rs+{0,4,8,12} -> 8 independent float4 loads, one round-trip.
//  Ticket: last-arriving block alone runs stage B (fixed row order ->
//    deterministic regardless of which block it is).
// mom1 == 0 analytically (reference's fp32 residual ~1e-7 is negligible at
// the 1e-3 output tolerance).
// ---------------------------------------------------------------------------
__global__ __launch_bounds__(576, 1) void tail_kernel(const float* __restrict__ mu,
                                                      const float* __restrict__ W,
                                                      float* __restrict__ out) {
    const int b  = blockIdx.x;    // 0..73
    const int t  = threadIdx.x;   // 0..575
    const int c4 = t % 144;
    const int rs = t / 144;       // 0..3

    __shared__ float4 park_s[3][144];
    __shared__ float4 park_q[3][144];
    __shared__ int    sh_last;

    // ---------------- Stage A: one round-trip fold of 16 rows --------------
    {
        const int i0 = b * ROWS_PER_RED + rs;   // rows i0, i0+4, i0+8, i0+12
        const float4 a0 = reinterpret_cast<const float4*>(&g_ps[i0     ][0])[c4];
        const float4 a1 = reinterpret_cast<const float4*>(&g_ps[i0 +  4][0])[c4];
        const float4 a2 = reinterpret_cast<const float4*>(&g_ps[i0 +  8][0])[c4];
        const float4 a3 = reinterpret_cast<const float4*>(&g_ps[i0 + 12][0])[c4];
        const float4 e0 = reinterpret_cast<const float4*>(&g_pq[i0     ][0])[c4];
        const float4 e1 = reinterpret_cast<const float4*>(&g_pq[i0 +  4][0])[c4];
        const float4 e2 = reinterpret_cast<const float4*>(&g_pq[i0 +  8][0])[c4];
        const float4 e3 = reinterpret_cast<const float4*>(&g_pq[i0 + 12][0])[c4];

        float4 s = make_float4((a0.x + a1.x) + (a2.x + a3.x),
                               (a0.y + a1.y) + (a2.y + a3.y),
                               (a0.z + a1.z) + (a2.z + a3.z),
                               (a0.w + a1.w) + (a2.w + a3.w));
        float4 q = make_float4((e0.x + e1.x) + (e2.x + e3.x),
                               (e0.y + e1.y) + (e2.y + e3.y),
                               (e0.z + e1.z) + (e2.z + e3.z),
                               (e0.w + e1.w) + (e2.w + e3.w));

        if (rs > 0) { park_s[rs - 1][c4] = s; park_q[rs - 1][c4] = q; }
        __syncthreads();
        if (rs == 0) {
            #pragma unroll
            for (int ph = 0; ph < 3; ph++) {
                float4 a = park_s[ph][c4];
                s.x += a.x; s.y += a.y; s.z += a.z; s.w += a.w;
                float4 e = park_q[ph][c4];
                q.x += e.x; q.y += e.y; q.z += e.z; q.w += e.w;
            }
            reinterpret_cast<float4*>(&g_ps2[b][0])[c4] = s;
            reinterpret_cast<float4*>(&g_pq2[b][0])[c4] = q;
        }
    }

    // ---------------- Ticket: last block continues, others exit -----------
    __threadfence();              // release our g_ps2/g_pq2 stores
    __syncthreads();
    if (t == 0) {
        const int ticket = atomicAdd(&g_cnt, 1);
        sh_last = (ticket == NRED - 1);
    }
    __syncthreads();
    if (!sh_last) return;

    __threadfence();              // acquire: all 74 blocks' stores visible

    // ---------------- Stage B: fold 74 rows (float4, phase-split) ---------
    float4 s = make_float4(0.f, 0.f, 0.f, 0.f);
    float4 q = make_float4(0.f, 0.f, 0.f, 0.f);
    #pragma unroll 5
    for (int i = rs; i < NRED; i += 4) {
        float4 a = reinterpret_cast<const float4*>(&g_ps2[i][0])[c4];
        s.x += a.x; s.y += a.y; s.z += a.z; s.w += a.w;
        float4 e = reinterpret_cast<const float4*>(&g_pq2[i][0])[c4];
        q.x += e.x; q.y += e.y; q.z += e.z; q.w += e.w;
    }
    __syncthreads();              // park_s/park_q reuse
    if (rs > 0) { park_s[rs - 1][c4] = s; park_q[rs - 1][c4] = q; }
    __syncthreads();

    __shared__ float4 tot_s[144];
    __shared__ float4 tot_q[144];
    if (rs == 0) {
        #pragma unroll
        for (int ph = 0; ph < 3; ph++) {
            float4 a = park_s[ph][c4];
            s.x += a.x; s.y += a.y; s.z += a.z; s.w += a.w;
            float4 e = park_q[ph][c4];
            q.x += e.x; q.y += e.y; q.z += e.z; q.w += e.w;
        }
        tot_s[c4] = s;
        tot_q[c4] = q;
    }
    __syncthreads();

    // ---------------- Cumulants + projection (thread t = column t) --------
    const float s2 = reinterpret_cast<const float*>(tot_s)[t];
    const float q2 = reinterpret_cast<const float*>(tot_q)[t];

    const float invN = 1.0f / (float)N_ROWS;
    const float m    = s2 * invN;
    const float mom2 = q2 * invN - m * m;

    const int j0 = 3 * t;
    const float d0 = m    - mu[j0 + 0];
    const float d1 = 0.f  - mu[j0 + 1];
    const float d2 = mom2 - mu[j0 + 2];

    float4 acc;
    acc.x = d0 * W[(j0 + 0) * 4 + 0] + d1 * W[(j0 + 1) * 4 + 0] + d2 * W[(j0 + 2) * 4 + 0];
    acc.y = d0 * W[(j0 + 0) * 4 + 1] + d1 * W[(j0 + 1) * 4 + 1] + d2 * W[(j0 + 2) * 4 + 1];
    acc.z = d0 * W[(j0 + 0) * 4 + 2] + d1 * W[(j0 + 1) * 4 + 2] + d2 * W[(j0 + 2) * 4 + 2];
    acc.w = d0 * W[(j0 + 0) * 4 + 3] + d1 * W[(j0 + 1) * 4 + 3] + d2 * W[(j0 + 2) * 4 + 3];

    __shared__ float4 sh3[576];
    sh3[t] = acc;
    __syncthreads();

    if (t < 64) {
        float4 a = sh3[t];
        for (int i = t + 64; i < 576; i += 64) {
            float4 bb = sh3[i];
            a.x += bb.x; a.y += bb.y; a.z += bb.z; a.w += bb.w;
        }
        sh3[t] = a;
    }
    __syncthreads();
    #pragma unroll
    for (int w = 32; w > 0; w >>= 1) {
        if (t < w) {
            float4 a = sh3[t], bb = sh3[t + w];
            a.x += bb.x; a.y += bb.y; a.z += bb.z; a.w += bb.w;
            sh3[t] = a;
        }
        __syncthreads();
    }

    if (t == 0) {
        out[0] = sh3[0].x;
        out[1] = sh3[0].y;
        out[2] = sh3[0].z;
        out[3] = sh3[0].w;
        g_cnt = 0;   // reset ticket for next graph replay (we are the last block)
    }
}

extern "C" void kernel_launch(void* const* d_in, const int* in_sizes, int n_in,
                              void* d_out, int out_size) {
    (void)in_sizes; (void)n_in; (void)out_size;
    const float* X  = (const float*)d_in[0];   // (200000, 576)
    const float* mu = (const float*)d_in[1];   // (1728,)
    const float* W  = (const float*)d_in[2];   // (1728, 4)
    float* out = (float*)d_out;                // (1, 4)

    pass1_kernel<<<NBLK, 576>>>(X);
    tail_kernel<<<NRED, 576>>>(mu, W, out);
}